// round 5
// baseline (speedup 1.0000x reference)
#include <cuda_runtime.h>

#define HID     30
#define SEQLEN  784
#define NCLS    10
#define B_MAX   16384

typedef unsigned long long u64;

// packed j-pair weights: cW2[k*16 + p] = (W_hh[2p][k], W_hh[2p+1][k])
__constant__ u64 cW2[HID * 16];

// staging (device-writable) + transposed inputs
__device__ u64   g_pack[HID * 16];
__device__ float g_xT[(size_t)SEQLEN * B_MAX];

// ---- packed f32x2 helpers ----
__device__ __forceinline__ u64 dup2(float v) {
    u64 r; asm("mov.b64 %0, {%1,%1};" : "=l"(r) : "f"(v)); return r;
}
__device__ __forceinline__ u64 pk2(float lo, float hi) {
    u64 r; asm("mov.b64 %0, {%1,%2};" : "=l"(r) : "f"(lo), "f"(hi)); return r;
}
__device__ __forceinline__ float2 up2(u64 v) {
    float2 f; asm("mov.b64 {%0,%1}, %2;" : "=f"(f.x), "=f"(f.y) : "l"(v)); return f;
}
__device__ __forceinline__ u64 fma2(u64 a, u64 b, u64 c) {
    u64 d; asm("fma.rn.f32x2 %0, %1, %2, %3;" : "=l"(d) : "l"(a), "l"(b), "l"(c)); return d;
}
__device__ __forceinline__ u64 mul2(u64 a, u64 b) {
    u64 d; asm("mul.rn.f32x2 %0, %1, %2;" : "=l"(d) : "l"(a), "l"(b)); return d;
}

// modReLU: sign(z) * relu(|z| + b)
__device__ __forceinline__ float mrelu(float z, float b) {
    float t = fabsf(z) + b;
    float r = fmaxf(t, 0.0f);
    unsigned u = __float_as_uint(r) | (__float_as_uint(z) & 0x80000000u);
    return __uint_as_float(u);
}

// ---- pack W_hh into j-pair u64s (staging; then D2D-copied to __constant__) ----
__global__ void pack_kernel(const float* __restrict__ W_hh) {
    int i = threadIdx.x;
    if (i < HID * 16) {
        int k = i >> 4, p = i & 15;
        u64 v = 0;
        if (p < 15) v = pk2(W_hh[(2 * p) * HID + k], W_hh[(2 * p + 1) * HID + k]);
        g_pack[i] = v;
    }
}

// ---- tiled transpose: inputs[B][SEQ] -> g_xT[SEQ][B] ----
__global__ void transpose_kernel(const float* __restrict__ in, int B) {
    __shared__ float tile[32][33];
    int rb = blockIdx.x * 32;      // row base
    int tb = blockIdx.y * 32;      // t base
    int tx = threadIdx.x, ty = threadIdx.y;
#pragma unroll
    for (int i = 0; i < 4; i++) {
        int row = rb + ty + i * 8, t = tb + tx;
        tile[ty + i * 8][tx] = (t < SEQLEN) ? in[(size_t)row * SEQLEN + t] : 0.0f;
    }
    __syncthreads();
#pragma unroll
    for (int i = 0; i < 4; i++) {
        int t = tb + ty + i * 8, row = rb + tx;
        if (t < SEQLEN) g_xT[(size_t)t * B + row] = tile[tx][ty + i * 8];
    }
}

__global__ __launch_bounds__(128, 1)
void rnn_modrelu_const(const float* __restrict__ W_ih,
                       const float* __restrict__ b_mod,
                       const float* __restrict__ W_lin,
                       const float* __restrict__ b_lin,
                       float* __restrict__ out, int B)
{
    __shared__ float sWlin[NCLS * HID];
    __shared__ float sblin[NCLS];
    __shared__ float sWih[HID];
    __shared__ float sbm[HID];

    const int tid = threadIdx.x;
    for (int i = tid; i < NCLS * HID; i += 128) sWlin[i] = W_lin[i];
    for (int i = tid; i < HID; i += 128) { sWih[i] = W_ih[i]; sbm[i] = b_mod[i]; }
    for (int i = tid; i < NCLS; i += 128) sblin[i] = b_lin[i];
    __syncthreads();

    const int row = blockIdx.x * blockDim.x + tid;
    if (row >= B) return;

    u64 wih2[15];
#pragma unroll
    for (int p = 0; p < 15; p++) wih2[p] = pk2(sWih[2 * p], sWih[2 * p + 1]);
    float bm[HID];
#pragma unroll
    for (int j = 0; j < HID; j++) bm[j] = sbm[j];

    float h[HID];
#pragma unroll
    for (int j = 0; j < HID; j++) h[j] = 0.0f;

    const float* xp = g_xT + row;     // coalesced: lanes read consecutive floats
    float x = xp[0];
    xp += B;

    for (int t = 0; t < SEQLEN; ++t) {
        float xn = (t + 1 < SEQLEN) ? *xp : 0.0f;   // coalesced prefetch
        xp += B;

        u64 xd = dup2(x);
        u64 z[15];
#pragma unroll
        for (int p = 0; p < 15; p++) z[p] = mul2(xd, wih2[p]);

#pragma unroll
        for (int k = 0; k < HID; k++) {
            u64 hd = dup2(h[k]);
            const ulonglong2* cr = (const ulonglong2*)&cW2[k * 16];  // const port
#pragma unroll
            for (int q = 0; q < 7; q++) {            // 7x LDCU.128 (uniform)
                ulonglong2 w = cr[q];
                z[2 * q]     = fma2(hd, w.x, z[2 * q]);
                z[2 * q + 1] = fma2(hd, w.y, z[2 * q + 1]);
            }
            z[14] = fma2(hd, cW2[k * 16 + 14], z[14]);  // LDCU.64
        }

#pragma unroll
        for (int p = 0; p < 15; p++) {
            float2 zz = up2(z[p]);
            h[2 * p]     = mrelu(zz.x, bm[2 * p]);
            h[2 * p + 1] = mrelu(zz.y, bm[2 * p + 1]);
        }
        x = xn;
    }

    float* orow = out + (size_t)row * NCLS;
#pragma unroll
    for (int c = 0; c < NCLS; c++) {
        float acc = sblin[c];
#pragma unroll
        for (int j = 0; j < HID; j++) acc = fmaf(h[j], sWlin[c * HID + j], acc);
        orow[c] = acc;
    }
}

extern "C" void kernel_launch(void* const* d_in, const int* in_sizes, int n_in,
                              void* d_out, int out_size)
{
    const float* inputs = (const float*)d_in[0];
    const float* W_ih   = (const float*)d_in[1];
    const float* W_hh   = (const float*)d_in[2];
    const float* b_mod  = (const float*)d_in[3];
    const float* W_lin  = (const float*)d_in[4];
    const float* b_lin  = (const float*)d_in[5];
    float* out = (float*)d_out;

    const int B = in_sizes[0] / SEQLEN;

    // 1) pack W_hh into j-pair u64 staging
    pack_kernel<<<1, HID * 16>>>(W_hh);

    // 2) transpose inputs -> g_xT[SEQ][B]
    dim3 tb(32, 8);
    dim3 tg(B / 32, (SEQLEN + 31) / 32);
    transpose_kernel<<<tg, tb>>>(inputs, B);

    // 3) stage packed weights into __constant__ (graph-capturable D2D)
    void* cptr = nullptr; void* pptr = nullptr;
    cudaGetSymbolAddress(&cptr, cW2);
    cudaGetSymbolAddress(&pptr, g_pack);
    cudaMemcpyAsync(cptr, pptr, sizeof(u64) * HID * 16, cudaMemcpyDeviceToDevice);

    // 4) main scan
    const int threads = 128;
    const int blocks = (B + threads - 1) / threads;
    rnn_modrelu_const<<<blocks, threads>>>(W_ih, b_mod, W_lin, b_lin, out, B);
}